// round 1
// baseline (speedup 1.0000x reference)
#include <cuda_runtime.h>
#include <cstddef>
#include <math.h>

// Problem constants
#define BB   16
#define SS   512
#define HH   4
#define DD   512
#define HIDD 2048
#define NHEADS (BB*HH)          // 64
#define MROWS (BB*SS)           // 8192

static const float SCALE_F = 0.04419417382415922f;   // 1/sqrt(512)

// ---------------- scratch (device globals; no allocation allowed) ----------
// head-major layout [b][h][s][d] (contiguous 512x512 per head)
__device__ float g_q [(size_t)NHEADS*SS*DD];
__device__ float g_k [(size_t)NHEADS*SS*DD];
__device__ float g_v [(size_t)NHEADS*SS*DD];
__device__ float g_ck[(size_t)NHEADS*SS*DD];
__device__ float g_cv[(size_t)NHEADS*SS*DD];
__device__ float g_s1[(size_t)NHEADS*SS*SS];
__device__ float g_s2[(size_t)NHEADS*SS*SS];
__device__ float g_ctx[(size_t)NHEADS*SS*DD];

// ---------------------------------------------------------------------------
// Projection GEMM: Y_w = X @ W_w^T + b_w   (NT), output remapped to
// head-major [b][h][s][d].  M=8192, N=2048, K=2048, 5 weights via blockIdx.z.
// 128x128x8 tile, 256 threads, 8x8 per-thread microtile.
// ---------------------------------------------------------------------------
struct ProjArgs {
    const float* X;
    const float* W[5];
    const float* bias[5];
    float*       Y[5];
};

__global__ __launch_bounds__(256) void proj_kernel(ProjArgs a) {
    const int w = blockIdx.z;
    const float* __restrict__ X    = a.X;
    const float* __restrict__ W    = a.W[w];
    const float* __restrict__ bias = a.bias[w];
    float* __restrict__ Y          = a.Y[w];

    const int m0 = blockIdx.y * 128;
    const int n0 = blockIdx.x * 128;

    __shared__ float As[8][128];
    __shared__ float Bs[8][128];

    const int tid     = threadIdx.x;
    const int loadRow = tid >> 1;        // 0..127
    const int loadCol = (tid & 1) * 4;   // 0 or 4
    const int ty      = tid >> 4;        // 0..15
    const int tx      = tid & 15;        // 0..15

    float acc[8][8];
#pragma unroll
    for (int i = 0; i < 8; i++)
#pragma unroll
        for (int j = 0; j < 8; j++) acc[i][j] = 0.f;

    const float* Aptr = X + (size_t)(m0 + loadRow) * HIDD + loadCol;
    const float* Bptr = W + (size_t)(n0 + loadRow) * HIDD + loadCol;

    for (int k0 = 0; k0 < HIDD; k0 += 8) {
        float4 av = *reinterpret_cast<const float4*>(Aptr + k0);
        float4 bv = *reinterpret_cast<const float4*>(Bptr + k0);
        As[loadCol + 0][loadRow] = av.x;
        As[loadCol + 1][loadRow] = av.y;
        As[loadCol + 2][loadRow] = av.z;
        As[loadCol + 3][loadRow] = av.w;
        Bs[loadCol + 0][loadRow] = bv.x;
        Bs[loadCol + 1][loadRow] = bv.y;
        Bs[loadCol + 2][loadRow] = bv.z;
        Bs[loadCol + 3][loadRow] = bv.w;
        __syncthreads();
#pragma unroll
        for (int kk = 0; kk < 8; kk++) {
            float ar[8], br[8];
            *reinterpret_cast<float4*>(&ar[0]) = *reinterpret_cast<const float4*>(&As[kk][ty * 8]);
            *reinterpret_cast<float4*>(&ar[4]) = *reinterpret_cast<const float4*>(&As[kk][ty * 8 + 4]);
            *reinterpret_cast<float4*>(&br[0]) = *reinterpret_cast<const float4*>(&Bs[kk][tx * 8]);
            *reinterpret_cast<float4*>(&br[4]) = *reinterpret_cast<const float4*>(&Bs[kk][tx * 8 + 4]);
#pragma unroll
            for (int i = 0; i < 8; i++)
#pragma unroll
                for (int j = 0; j < 8; j++) acc[i][j] = fmaf(ar[i], br[j], acc[i][j]);
        }
        __syncthreads();
    }

    // epilogue: add bias, remap (r=b*S+s, c=h*D+d) -> [b][h][s][d]
    const int r0   = m0 + ty * 8;
    const int c0   = n0 + tx * 8;
    const int b    = r0 >> 9;      // S = 512
    const int h    = c0 >> 9;      // D = 512
    const int dloc = c0 & 511;

    float bvals[8];
#pragma unroll
    for (int j = 0; j < 8; j++) bvals[j] = bias[c0 + j];

#pragma unroll
    for (int i = 0; i < 8; i++) {
        const int s = (r0 + i) & 511;
        float* out = Y + (((size_t)(b * HH + h) * SS + s) * DD + dloc);
#pragma unroll
        for (int j = 0; j < 8; j++) out[j] = acc[i][j] + bvals[j];
    }
}

// ---------------------------------------------------------------------------
// Batched per-head GEMM: 64 heads, M=N=512, K=512.
// TB=true:  C = alpha * A @ B^T
// TB=false: C = alpha * A @ B
// Per-batch offsets: A += z*sA, B += z*sB, C += (z/H)*sCb + (z%H)*sCh
// ---------------------------------------------------------------------------
template <bool TB>
__global__ __launch_bounds__(256) void bgemm_kernel(
    const float* __restrict__ A, size_t sA, int lda,
    const float* __restrict__ Bm, size_t sB, int ldb,
    float* __restrict__ C, size_t sCb, size_t sCh, int ldc,
    int K, float alpha)
{
    const int z = blockIdx.z;
    A  += (size_t)z * sA;
    Bm += (size_t)z * sB;
    C  += (size_t)(z / HH) * sCb + (size_t)(z % HH) * sCh;

    const int m0 = blockIdx.y * 128;
    const int n0 = blockIdx.x * 128;

    __shared__ float As[8][128];
    __shared__ float Bs[8][128];

    const int tid     = threadIdx.x;
    const int loadRow = tid >> 1;
    const int loadCol = (tid & 1) * 4;
    const int ty      = tid >> 4;
    const int tx      = tid & 15;

    float acc[8][8];
#pragma unroll
    for (int i = 0; i < 8; i++)
#pragma unroll
        for (int j = 0; j < 8; j++) acc[i][j] = 0.f;

    const float* Aptr = A + (size_t)(m0 + loadRow) * lda + loadCol;
    const float* BptrT = Bm + (size_t)(n0 + loadRow) * ldb + loadCol;                  // TB path
    const float* BptrN = Bm + (size_t)(tid >> 5) * ldb + n0 + (tid & 31) * 4;          // NN path

    for (int k0 = 0; k0 < K; k0 += 8) {
        float4 av = *reinterpret_cast<const float4*>(Aptr + k0);
        As[loadCol + 0][loadRow] = av.x;
        As[loadCol + 1][loadRow] = av.y;
        As[loadCol + 2][loadRow] = av.z;
        As[loadCol + 3][loadRow] = av.w;
        if (TB) {
            float4 bv = *reinterpret_cast<const float4*>(BptrT + k0);
            Bs[loadCol + 0][loadRow] = bv.x;
            Bs[loadCol + 1][loadRow] = bv.y;
            Bs[loadCol + 2][loadRow] = bv.z;
            Bs[loadCol + 3][loadRow] = bv.w;
        } else {
            float4 bv = *reinterpret_cast<const float4*>(BptrN + (size_t)k0 * ldb);
            *reinterpret_cast<float4*>(&Bs[tid >> 5][(tid & 31) * 4]) = bv;
        }
        __syncthreads();
#pragma unroll
        for (int kk = 0; kk < 8; kk++) {
            float ar[8], br[8];
            *reinterpret_cast<float4*>(&ar[0]) = *reinterpret_cast<const float4*>(&As[kk][ty * 8]);
            *reinterpret_cast<float4*>(&ar[4]) = *reinterpret_cast<const float4*>(&As[kk][ty * 8 + 4]);
            *reinterpret_cast<float4*>(&br[0]) = *reinterpret_cast<const float4*>(&Bs[kk][tx * 8]);
            *reinterpret_cast<float4*>(&br[4]) = *reinterpret_cast<const float4*>(&Bs[kk][tx * 8 + 4]);
#pragma unroll
            for (int i = 0; i < 8; i++)
#pragma unroll
                for (int j = 0; j < 8; j++) acc[i][j] = fmaf(ar[i], br[j], acc[i][j]);
        }
        __syncthreads();
    }

    const int r0 = m0 + ty * 8;
    const int c0 = n0 + tx * 8;
#pragma unroll
    for (int i = 0; i < 8; i++) {
        float* out = C + (size_t)(r0 + i) * ldc + c0;
#pragma unroll
        for (int j = 0; j < 8; j++) out[j] = alpha * acc[i][j];
    }
}

// ---------------------------------------------------------------------------
// Row softmax over 512 columns, in place.  One 128-thread block per row.
// ---------------------------------------------------------------------------
__global__ __launch_bounds__(128) void softmax_kernel(float* __restrict__ P) {
    const size_t row = blockIdx.x;
    float* p = P + row * SS;
    const int t = threadIdx.x;         // 0..127, 4 elems each

    float4 v = reinterpret_cast<float4*>(p)[t];

    float m = fmaxf(fmaxf(v.x, v.y), fmaxf(v.z, v.w));
#pragma unroll
    for (int o = 16; o; o >>= 1) m = fmaxf(m, __shfl_xor_sync(0xffffffffu, m, o));
    __shared__ float redm[4];
    if ((t & 31) == 0) redm[t >> 5] = m;
    __syncthreads();
    m = fmaxf(fmaxf(redm[0], redm[1]), fmaxf(redm[2], redm[3]));

    v.x = expf(v.x - m);
    v.y = expf(v.y - m);
    v.z = expf(v.z - m);
    v.w = expf(v.w - m);

    float s = v.x + v.y + v.z + v.w;
#pragma unroll
    for (int o = 16; o; o >>= 1) s += __shfl_xor_sync(0xffffffffu, s, o);
    __shared__ float reds[4];
    if ((t & 31) == 0) reds[t >> 5] = s;
    __syncthreads();
    s = reds[0] + reds[1] + reds[2] + reds[3];

    const float inv = 1.0f / s;
    v.x *= inv; v.y *= inv; v.z *= inv; v.w *= inv;
    reinterpret_cast<float4*>(p)[t] = v;
}

// ---------------------------------------------------------------------------
extern "C" void kernel_launch(void* const* d_in, const int* in_sizes, int n_in,
                              void* d_out, int out_size)
{
    const float* X   = (const float*)d_in[0];
    const float* Wq  = (const float*)d_in[1];
    const float* bq  = (const float*)d_in[2];
    const float* Wk  = (const float*)d_in[3];
    const float* bk  = (const float*)d_in[4];
    const float* Wv  = (const float*)d_in[5];
    const float* bv  = (const float*)d_in[6];
    const float* Wck = (const float*)d_in[7];
    const float* bck = (const float*)d_in[8];
    const float* Wcv = (const float*)d_in[9];
    const float* bcv = (const float*)d_in[10];

    float *q, *k, *v, *ck, *cv, *s1, *s2, *ctx;
    cudaGetSymbolAddress((void**)&q,   g_q);
    cudaGetSymbolAddress((void**)&k,   g_k);
    cudaGetSymbolAddress((void**)&v,   g_v);
    cudaGetSymbolAddress((void**)&ck,  g_ck);
    cudaGetSymbolAddress((void**)&cv,  g_cv);
    cudaGetSymbolAddress((void**)&s1,  g_s1);
    cudaGetSymbolAddress((void**)&s2,  g_s2);
    cudaGetSymbolAddress((void**)&ctx, g_ctx);

    ProjArgs pa;
    pa.X = X;
    pa.W[0] = Wq;  pa.bias[0] = bq;  pa.Y[0] = q;
    pa.W[1] = Wk;  pa.bias[1] = bk;  pa.Y[1] = k;
    pa.W[2] = Wv;  pa.bias[2] = bv;  pa.Y[2] = v;
    pa.W[3] = Wck; pa.bias[3] = bck; pa.Y[3] = ck;
    pa.W[4] = Wcv; pa.bias[4] = bcv; pa.Y[4] = cv;

    // 1) five projections -> head-major buffers
    proj_kernel<<<dim3(HIDD / 128, MROWS / 128, 5), 256>>>(pa);

    const size_t SD = (size_t)SS * DD;   // 512*512
    const size_t SSQ = (size_t)SS * SS;
    dim3 g(SS / 128, SS / 128, NHEADS);  // (4,4,64)

    // 2) s1 = q @ k^T
    bgemm_kernel<true><<<g, 256>>>(q, SD, DD, k, SD, DD,
                                   s1, (size_t)HH * SSQ, SSQ, SS, DD, 1.0f);
    // 3) s2 = (s1 @ ck^T) * SCALE
    bgemm_kernel<true><<<g, 256>>>(s1, SSQ, SS, ck, SD, DD,
                                   s2, (size_t)HH * SSQ, SSQ, SS, SS, SCALE_F);
    // 4) softmax rows of s2 (in place) -> probs
    softmax_kernel<<<NHEADS * SS, 128>>>(s2);
    // 5) ctx = probs @ v
    bgemm_kernel<false><<<g, 256>>>(s2, SSQ, SS, v, SD, DD,
                                    ctx, (size_t)HH * SD, SD, DD, SS, 1.0f);
    // 6) out = ctx @ cv, written to [b, s, h*D+e] layout
    bgemm_kernel<false><<<g, 256>>>(ctx, SD, DD, cv, SD, DD,
                                    (float*)d_out, (size_t)SS * HIDD, (size_t)DD, HIDD,
                                    DD, 1.0f);
}